// round 14
// baseline (speedup 1.0000x reference)
#include <cuda_runtime.h>
#include <cuda_fp16.h>
#include <math.h>

#define NN 100000
#define EE 1600000
#define DIM 128
#define HID 16
#define HEADS 4
#define F1 (HEADS * HID)   // 64
#define NEG 0.2f

#define SCAN_BLK 512
#define NBLK ((NN + SCAN_BLK - 1) / SCAN_BLK)   // 196

// gemm tiling: 128 nodes/block, 128 threads, 8 nodes x 8 channels per thread
#define GN 128
#define XPITCH 129
#define GEMM_SMEM ((GN * XPITCH + DIM * F1) * 4)   // 98816 bytes

// ---------------- scratch (static device globals; no allocation) -------------
__device__ __align__(16) __half g_h1h[NN * F1];   // layer-1 features (fp16)
__device__ __align__(16) float g_as1[NN * HEADS];
__device__ __align__(16) float g_ad1[NN * HEADS];
__device__ __align__(16) float4 g_pk2[NN];        // {h3.x, h3.y, as2, 0} per node
__device__ float g_ad2[NN];

__device__ int g_deg[NN];
__device__ int g_offs[NN + 1];
__device__ int g_cur[NN];
__device__ int g_bsum[256];
__device__ unsigned long long g_ctr = 0ULL;   // epoch ticket counter (never reset)
__device__ int g_csr_src[EE];                 // self-loops handled implicitly

// ---------------- helpers ----------------------------------------------------
__device__ __forceinline__ float lrelu(float v) {
    return v > 0.0f ? v : NEG * v;
}

__device__ __forceinline__ unsigned long long packf2(float lo, float hi) {
    unsigned long long r;
    asm("mov.b64 %0, {%1, %2};" : "=l"(r) : "f"(lo), "f"(hi));
    return r;
}
__device__ __forceinline__ void unpackf2(unsigned long long v, float& lo, float& hi) {
    asm("mov.b64 {%0, %1}, %2;" : "=f"(lo), "=f"(hi) : "l"(v));
}
__device__ __forceinline__ void fmaf2(unsigned long long& d, unsigned long long a,
                                      unsigned long long b) {
    asm("fma.rn.f32x2 %0, %1, %2, %0;" : "+l"(d) : "l"(a), "l"(b));
}

// ---------------- kernels ----------------------------------------------------

// h1 = x @ W1 (register-tiled 8 nodes x 8 ch per thread, packed f32x2 FMA).
__global__ __launch_bounds__(128, 2) void k_gemm1(
    const float* __restrict__ x, const float* __restrict__ W1,
    const float* __restrict__ asrc, const float* __restrict__ adst) {

    extern __shared__ float sm[];
    float* xs = sm;                    // [GN][XPITCH]
    float* Ws = sm + GN * XPITCH;      // [DIM][F1] row-major

    int tid = threadIdx.x;
    int n0 = blockIdx.x * GN;

    #pragma unroll
    for (int i = tid; i < DIM * F1 / 4; i += 128)
        ((float4*)Ws)[i] = ((const float4*)W1)[i];

    for (int i = tid; i < GN * 32; i += 128) {
        int r = i >> 5, c4 = i & 31;
        float4 v = (n0 + r < NN)
                 ? ((const float4*)(x + (size_t)(n0 + r) * DIM))[c4]
                 : make_float4(0.f, 0.f, 0.f, 0.f);
        float* dp = xs + r * XPITCH + c4 * 4;
        dp[0] = v.x; dp[1] = v.y; dp[2] = v.z; dp[3] = v.w;
    }
    __syncthreads();

    int ct = tid & 7;
    int nt = tid >> 3;

    unsigned long long acc[8][4];
    #pragma unroll
    for (int j = 0; j < 8; j++)
        #pragma unroll
        for (int p = 0; p < 4; p++) acc[j][p] = 0ULL;

    const float* xb = xs + nt * 8 * XPITCH;

    #pragma unroll 2
    for (int k = 0; k < DIM; k++) {
        float4 w0 = *(const float4*)(Ws + k * F1 + ct * 8);
        float4 w1 = *(const float4*)(Ws + k * F1 + ct * 8 + 4);
        unsigned long long wp[4];
        wp[0] = packf2(w0.x, w0.y);
        wp[1] = packf2(w0.z, w0.w);
        wp[2] = packf2(w1.x, w1.y);
        wp[3] = packf2(w1.z, w1.w);
        #pragma unroll
        for (int j = 0; j < 8; j++) {
            float xv = xb[j * XPITCH + k];
            unsigned long long xx = packf2(xv, xv);
            fmaf2(acc[j][0], xx, wp[0]);
            fmaf2(acc[j][1], xx, wp[1]);
            fmaf2(acc[j][2], xx, wp[2]);
            fmaf2(acc[j][3], xx, wp[3]);
        }
    }

    float ar[8], dr[8];
    #pragma unroll
    for (int i = 0; i < 8; i++) {
        ar[i] = __ldg(asrc + ct * 8 + i);
        dr[i] = __ldg(adst + ct * 8 + i);
    }

    #pragma unroll
    for (int j = 0; j < 8; j++) {
        int n = n0 + nt * 8 + j;
        float a[8];
        unpackf2(acc[j][0], a[0], a[1]);
        unpackf2(acc[j][1], a[2], a[3]);
        unpackf2(acc[j][2], a[4], a[5]);
        unpackf2(acc[j][3], a[6], a[7]);

        float ps = 0.f, pd = 0.f;
        #pragma unroll
        for (int i = 0; i < 8; i++) {
            ps += a[i] * ar[i];
            pd += a[i] * dr[i];
        }
        ps += __shfl_xor_sync(0xffffffffu, ps, 1);
        pd += __shfl_xor_sync(0xffffffffu, pd, 1);

        if (n < NN) {
            union { __half2 h2[4]; uint4 u; } pk;
            pk.h2[0] = __floats2half2_rn(a[0], a[1]);
            pk.h2[1] = __floats2half2_rn(a[2], a[3]);
            pk.h2[2] = __floats2half2_rn(a[4], a[5]);
            pk.h2[3] = __floats2half2_rn(a[6], a[7]);
            *(uint4*)(g_h1h + (size_t)n * F1 + ct * 8) = pk.u;
            if ((ct & 1) == 0) {
                int h = ct >> 1;
                g_as1[n * HEADS + h] = ps;
                g_ad1[n * HEADS + h] = pd;
            }
        }
    }
}

// ---------------- CSR build (real edges only; self-loops implicit) -----------
// 8 edges per thread (EE divisible by 8)
__global__ void k_count(const int* __restrict__ ei) {
    int t = blockIdx.x * blockDim.x + threadIdx.x;
    if (t >= EE / 8) return;
    int e = t * 8;
    int4 a = *(const int4*)(ei + EE + e);
    int4 b = *(const int4*)(ei + EE + e + 4);
    atomicAdd(&g_deg[a.x], 1); atomicAdd(&g_deg[a.y], 1);
    atomicAdd(&g_deg[a.z], 1); atomicAdd(&g_deg[a.w], 1);
    atomicAdd(&g_deg[b.x], 1); atomicAdd(&g_deg[b.y], 1);
    atomicAdd(&g_deg[b.z], 1); atomicAdd(&g_deg[b.w], 1);
}

// Fused single-pass scan; all NBLK=196 blocks resident -> grid spin is safe.
// Also zeroes g_deg for the next replay (static init covers the first call).
__global__ __launch_bounds__(SCAN_BLK) void k_scanF() {
    __shared__ int sh[SCAN_BLK];
    __shared__ int s_prefix;
    int t = threadIdx.x;
    int b = blockIdx.x;
    int i = b * SCAN_BLK + t;
    int v = 0;
    if (i < NN) { v = g_deg[i]; g_deg[i] = 0; }
    sh[t] = v;
    __syncthreads();
    #pragma unroll
    for (int off = 1; off < SCAN_BLK; off <<= 1) {
        int add = (t >= off) ? sh[t - off] : 0;
        __syncthreads();
        sh[t] += add;
        __syncthreads();
    }
    int incl = sh[t];

    if (t == SCAN_BLK - 1) {
        g_bsum[b] = incl;
        __threadfence();
        unsigned long long old = atomicAdd(&g_ctr, 1ULL);
        unsigned long long target = (old / NBLK + 1ULL) * NBLK;
        while (atomicAdd(&g_ctr, 0ULL) < target) { }
    }
    __syncthreads();

    if (t < 32) {
        volatile int* vb = g_bsum;
        int p = 0;
        for (int j = t; j < b; j += 32) p += vb[j];
        #pragma unroll
        for (int o = 16; o > 0; o >>= 1)
            p += __shfl_down_sync(0xffffffffu, p, o);
        if (t == 0) s_prefix = p;
    }
    __syncthreads();

    if (i < NN) {
        int o = s_prefix + incl - v;
        g_offs[i] = o;
        g_cur[i] = o;
    }
    if (i == NN - 1) g_offs[NN] = EE;
}

// 2 edges per thread: maximize concurrent atomic chains (latency-bound kernel)
__global__ void k_scatter(const int* __restrict__ ei) {
    int t = blockIdx.x * blockDim.x + threadIdx.x;
    if (t >= EE / 2) return;
    int e = t * 2;
    int2 sv = *(const int2*)(ei + e);
    int2 dv = *(const int2*)(ei + EE + e);
    int p0 = atomicAdd(&g_cur[dv.x], 1);
    int p1 = atomicAdd(&g_cur[dv.y], 1);
    g_csr_src[p0] = sv.x;
    g_csr_src[p1] = sv.y;
}

// ---------------- layer-1 aggregation + fused l2prep --------------------------
// One warp per dst node; batch-of-8-edge choreography; self-loop added
// directly (no CSR entry).
__global__ __launch_bounds__(256) void k_agg1(
    const float* __restrict__ b1, const float* __restrict__ W2,
    const float* __restrict__ as2, const float* __restrict__ ad2) {

    const unsigned FULL = 0xffffffffu;
    int lane = threadIdx.x & 31;
    int n = blockIdx.x * 8 + (threadIdx.x >> 5);
    if (n >= NN) return;

    int h_w = lane & 3;        // head for weight role
    int e_w = lane >> 2;       // edge slot for weight role
    int h_acc = lane >> 3;     // head for accumulation role
    int c = 2 * lane;

    float ad_w = __ldg(g_ad1 + n * 4 + h_w);
    int start = __ldg(g_offs + n);
    int end = __ldg(g_offs + n + 1);

    // self-loop contribution (weight exp(lrelu(as[n]+ad[n])) per head)
    float av_s = __ldg(g_as1 + n * 4 + h_acc);
    float ad_s = __ldg(g_ad1 + n * 4 + h_acc);
    float w_s = __expf(lrelu(av_s + ad_s));
    float2 qs = __half22float2(*(const __half2*)(g_h1h + (size_t)n * F1 + c));
    float acc0 = w_s * qs.x, acc1 = w_s * qs.y, wsum = w_s;

    for (int base = start; base < end; base += 8) {
        int li = base + (lane & 7);
        int idx = __ldg(g_csr_src + (li < EE ? li : EE - 1));

        int s_w = __shfl_sync(FULL, idx, e_w);
        float av = __ldg(g_as1 + s_w * 4 + h_w);
        float w = __expf(lrelu(av + ad_w));
        if (base + e_w >= end) w = 0.f;

        #pragma unroll
        for (int e = 0; e < 8; e++) {
            int s_e = __shfl_sync(FULL, idx, e);
            float w_e = __shfl_sync(FULL, w, e * 4 + h_acc);
            float2 q = __half22float2(
                *(const __half2*)(g_h1h + (size_t)s_e * F1 + c));
            acc0 += w_e * q.x;
            acc1 += w_e * q.y;
            wsum += w_e;
        }
    }

    float inv = 1.0f / (wsum + 1e-16f);
    int c0 = c, c1 = c + 1;
    float v0 = acc0 * inv + b1[c0];
    float v1 = acc1 * inv + b1[c1];
    v0 = v0 > 0.f ? v0 : expm1f(v0);          // ELU
    v1 = v1 > 0.f ? v1 : expm1f(v1);

    float p0 = v0 * W2[c0 * 2 + 0] + v1 * W2[c1 * 2 + 0];
    float p1 = v0 * W2[c0 * 2 + 1] + v1 * W2[c1 * 2 + 1];
    #pragma unroll
    for (int o = 16; o > 0; o >>= 1) {
        p0 += __shfl_down_sync(FULL, p0, o);
        p1 += __shfl_down_sync(FULL, p1, o);
    }
    if (lane == 0) {
        float s2v = p0 * as2[0] + p1 * as2[1];
        g_pk2[n] = make_float4(p0, p1, s2v, 0.f);
        g_ad2[n] = p0 * ad2[0] + p1 * ad2[1];
    }
}

// ---------------- layer-2 aggregation + output: half-warp per node ------------
// One float4 LDG per edge; self-loop added by sub-lane 0 directly.
__global__ __launch_bounds__(256) void k_agg2(
    float* __restrict__ out, const float* __restrict__ b2) {

    int sub = threadIdx.x & 15;
    int n = blockIdx.x * 16 + (threadIdx.x >> 4);
    if (n >= NN) return;

    float ad = g_ad2[n];
    int start = __ldg(g_offs + n);
    int end = __ldg(g_offs + n + 1);

    float a0 = 0.f, a1 = 0.f, wsum = 0.f;
    if (sub == 0) {   // self-loop
        float4 pk = g_pk2[n];
        float w = __expf(lrelu(pk.z + ad));
        a0 = w * pk.x; a1 = w * pk.y; wsum = w;
    }
    for (int i = start + sub; i < end; i += 16) {
        int s = __ldg(g_csr_src + i);
        float4 pk = g_pk2[s];
        float w = __expf(lrelu(pk.z + ad));
        a0 += w * pk.x;
        a1 += w * pk.y;
        wsum += w;
    }
    #pragma unroll
    for (int o = 8; o > 0; o >>= 1) {
        a0   += __shfl_down_sync(0xffffffffu, a0, o, 16);
        a1   += __shfl_down_sync(0xffffffffu, a1, o, 16);
        wsum += __shfl_down_sync(0xffffffffu, wsum, o, 16);
    }
    if (sub == 0) {
        float inv = 1.0f / (wsum + 1e-16f);
        out[n * 2 + 0] = a0 * inv + b2[0];
        out[n * 2 + 1] = a1 * inv + b2[1];
    }
}

// ---------------- launch ------------------------------------------------------
extern "C" void kernel_launch(void* const* d_in, const int* in_sizes, int n_in,
                              void* d_out, int out_size) {
    const float* x    = (const float*)d_in[0];
    const int*   ei   = (const int*)  d_in[1];
    const float* W1   = (const float*)d_in[2];
    const float* as1  = (const float*)d_in[3];
    const float* ad1  = (const float*)d_in[4];
    const float* b1   = (const float*)d_in[5];
    const float* W2   = (const float*)d_in[6];
    const float* as2  = (const float*)d_in[7];
    const float* ad2  = (const float*)d_in[8];
    const float* b2   = (const float*)d_in[9];
    float* out = (float*)d_out;

    // One-time host-side resources (host objects only; no device allocation).
    static cudaStream_t s2 = nullptr;
    static cudaEvent_t evFork = nullptr, evJoin = nullptr;
    if (!s2) {
        cudaStreamCreateWithFlags(&s2, cudaStreamNonBlocking);
        cudaEventCreateWithFlags(&evFork, cudaEventDisableTiming);
        cudaEventCreateWithFlags(&evJoin, cudaEventDisableTiming);
        cudaFuncSetAttribute(k_gemm1,
            cudaFuncAttributeMaxDynamicSharedMemorySize, GEMM_SMEM);
    }

    const int T = 256;

    // Fork: CSR build chain (depends only on ei) on s2, concurrent with GEMM.
    cudaEventRecord(evFork, 0);
    cudaStreamWaitEvent(s2, evFork, 0);

    k_gemm1<<<(NN + GN - 1) / GN, 128, GEMM_SMEM>>>(x, W1, as1, ad1);

    k_count<<<(EE / 8 + T - 1) / T, T, 0, s2>>>(ei);
    k_scanF<<<NBLK, SCAN_BLK, 0, s2>>>();
    k_scatter<<<(EE / 2 + T - 1) / T, T, 0, s2>>>(ei);

    // Join
    cudaEventRecord(evJoin, s2);
    cudaStreamWaitEvent(0, evJoin, 0);

    k_agg1<<<(NN + 7) / 8, T>>>(b1, W2, as2, ad2);
    k_agg2<<<(NN + 15) / 16, T>>>(out, b2);
}

// round 15
// speedup vs baseline: 1.0442x; 1.0442x over previous
#include <cuda_runtime.h>
#include <cuda_fp16.h>
#include <math.h>

#define NN 100000
#define EE 1600000
#define ETOT (EE + NN)
#define DIM 128
#define HID 16
#define HEADS 4
#define F1 (HEADS * HID)   // 64
#define NEG 0.2f

#define SCAN_BLK 512
#define NBLK ((NN + SCAN_BLK - 1) / SCAN_BLK)   // 196

// gemm tiling: 128 nodes/block, 128 threads, 8 nodes x 8 channels per thread
#define GN 128
#define XPITCH 129
#define GEMM_SMEM ((GN * XPITCH + DIM * F1) * 4)   // 98816 bytes

// ---------------- scratch (static device globals; no allocation) -------------
__device__ __align__(16) __half g_h1h[NN * F1];   // layer-1 features (fp16)
__device__ __align__(16) float g_as1[NN * HEADS];
__device__ __align__(16) float g_ad1[NN * HEADS];
__device__ __align__(16) float4 g_pk2[NN];        // {h3.x, h3.y, as2, 0} per node
__device__ float g_ad2[NN];

__device__ int g_deg[NN];
__device__ int g_offs[NN + 1];
__device__ int g_cur[NN];
__device__ int g_bsum[256];
__device__ unsigned long long g_ctr = 0ULL;   // epoch ticket counter (never reset)
__device__ int g_csr_src[ETOT];

// ---------------- helpers ----------------------------------------------------
__device__ __forceinline__ float lrelu(float v) {
    return v > 0.0f ? v : NEG * v;
}

__device__ __forceinline__ unsigned long long packf2(float lo, float hi) {
    unsigned long long r;
    asm("mov.b64 %0, {%1, %2};" : "=l"(r) : "f"(lo), "f"(hi));
    return r;
}
__device__ __forceinline__ void unpackf2(unsigned long long v, float& lo, float& hi) {
    asm("mov.b64 {%0, %1}, %2;" : "=f"(lo), "=f"(hi) : "l"(v));
}
__device__ __forceinline__ void fmaf2(unsigned long long& d, unsigned long long a,
                                      unsigned long long b) {
    asm("fma.rn.f32x2 %0, %1, %2, %0;" : "+l"(d) : "l"(a), "l"(b));
}

// ---------------- kernels ----------------------------------------------------

// h1 = x @ W1 (register-tiled 8 nodes x 8 ch per thread, packed f32x2 FMA).
__global__ __launch_bounds__(128, 2) void k_gemm1(
    const float* __restrict__ x, const float* __restrict__ W1,
    const float* __restrict__ asrc, const float* __restrict__ adst) {

    extern __shared__ float sm[];
    float* xs = sm;                    // [GN][XPITCH]
    float* Ws = sm + GN * XPITCH;      // [DIM][F1] row-major

    int tid = threadIdx.x;
    int n0 = blockIdx.x * GN;

    #pragma unroll
    for (int i = tid; i < DIM * F1 / 4; i += 128)
        ((float4*)Ws)[i] = ((const float4*)W1)[i];

    for (int i = tid; i < GN * 32; i += 128) {
        int r = i >> 5, c4 = i & 31;
        float4 v = (n0 + r < NN)
                 ? ((const float4*)(x + (size_t)(n0 + r) * DIM))[c4]
                 : make_float4(0.f, 0.f, 0.f, 0.f);
        float* dp = xs + r * XPITCH + c4 * 4;
        dp[0] = v.x; dp[1] = v.y; dp[2] = v.z; dp[3] = v.w;
    }
    __syncthreads();

    int ct = tid & 7;
    int nt = tid >> 3;

    unsigned long long acc[8][4];
    #pragma unroll
    for (int j = 0; j < 8; j++)
        #pragma unroll
        for (int p = 0; p < 4; p++) acc[j][p] = 0ULL;

    const float* xb = xs + nt * 8 * XPITCH;

    #pragma unroll 2
    for (int k = 0; k < DIM; k++) {
        float4 w0 = *(const float4*)(Ws + k * F1 + ct * 8);
        float4 w1 = *(const float4*)(Ws + k * F1 + ct * 8 + 4);
        unsigned long long wp[4];
        wp[0] = packf2(w0.x, w0.y);
        wp[1] = packf2(w0.z, w0.w);
        wp[2] = packf2(w1.x, w1.y);
        wp[3] = packf2(w1.z, w1.w);
        #pragma unroll
        for (int j = 0; j < 8; j++) {
            float xv = xb[j * XPITCH + k];
            unsigned long long xx = packf2(xv, xv);
            fmaf2(acc[j][0], xx, wp[0]);
            fmaf2(acc[j][1], xx, wp[1]);
            fmaf2(acc[j][2], xx, wp[2]);
            fmaf2(acc[j][3], xx, wp[3]);
        }
    }

    float ar[8], dr[8];
    #pragma unroll
    for (int i = 0; i < 8; i++) {
        ar[i] = __ldg(asrc + ct * 8 + i);
        dr[i] = __ldg(adst + ct * 8 + i);
    }

    #pragma unroll
    for (int j = 0; j < 8; j++) {
        int n = n0 + nt * 8 + j;
        float a[8];
        unpackf2(acc[j][0], a[0], a[1]);
        unpackf2(acc[j][1], a[2], a[3]);
        unpackf2(acc[j][2], a[4], a[5]);
        unpackf2(acc[j][3], a[6], a[7]);

        float ps = 0.f, pd = 0.f;
        #pragma unroll
        for (int i = 0; i < 8; i++) {
            ps += a[i] * ar[i];
            pd += a[i] * dr[i];
        }
        ps += __shfl_xor_sync(0xffffffffu, ps, 1);
        pd += __shfl_xor_sync(0xffffffffu, pd, 1);

        if (n < NN) {
            union { __half2 h2[4]; uint4 u; } pk;
            pk.h2[0] = __floats2half2_rn(a[0], a[1]);
            pk.h2[1] = __floats2half2_rn(a[2], a[3]);
            pk.h2[2] = __floats2half2_rn(a[4], a[5]);
            pk.h2[3] = __floats2half2_rn(a[6], a[7]);
            *(uint4*)(g_h1h + (size_t)n * F1 + ct * 8) = pk.u;
            if ((ct & 1) == 0) {
                int h = ct >> 1;
                g_as1[n * HEADS + h] = ps;
                g_ad1[n * HEADS + h] = pd;
            }
        }
    }
}

// ---------------- CSR build ---------------------------------------------------
// 8 edges per thread for MLP (ETOT and EE divisible by 8)
__global__ void k_count(const int* __restrict__ ei) {
    int t = blockIdx.x * blockDim.x + threadIdx.x;
    if (t >= ETOT / 8) return;
    int e = t * 8;
    if (e < EE) {
        int4 a = *(const int4*)(ei + EE + e);
        int4 b = *(const int4*)(ei + EE + e + 4);
        atomicAdd(&g_deg[a.x], 1); atomicAdd(&g_deg[a.y], 1);
        atomicAdd(&g_deg[a.z], 1); atomicAdd(&g_deg[a.w], 1);
        atomicAdd(&g_deg[b.x], 1); atomicAdd(&g_deg[b.y], 1);
        atomicAdd(&g_deg[b.z], 1); atomicAdd(&g_deg[b.w], 1);
    } else {
        int n = e - EE;
        #pragma unroll
        for (int j = 0; j < 8; j++) atomicAdd(&g_deg[n + j], 1);
    }
}

// Fused single-pass scan; all NBLK=196 blocks resident -> grid spin is safe.
// Also zeroes g_deg for the next replay (static init covers the first call).
__global__ __launch_bounds__(SCAN_BLK) void k_scanF() {
    __shared__ int sh[SCAN_BLK];
    __shared__ int s_prefix;
    int t = threadIdx.x;
    int b = blockIdx.x;
    int i = b * SCAN_BLK + t;
    int v = 0;
    if (i < NN) { v = g_deg[i]; g_deg[i] = 0; }
    sh[t] = v;
    __syncthreads();
    #pragma unroll
    for (int off = 1; off < SCAN_BLK; off <<= 1) {
        int add = (t >= off) ? sh[t - off] : 0;
        __syncthreads();
        sh[t] += add;
        __syncthreads();
    }
    int incl = sh[t];

    if (t == SCAN_BLK - 1) {
        g_bsum[b] = incl;
        __threadfence();
        unsigned long long old = atomicAdd(&g_ctr, 1ULL);
        unsigned long long target = (old / NBLK + 1ULL) * NBLK;
        while (atomicAdd(&g_ctr, 0ULL) < target) { }
    }
    __syncthreads();

    if (t < 32) {
        volatile int* vb = g_bsum;
        int p = 0;
        for (int j = t; j < b; j += 32) p += vb[j];
        #pragma unroll
        for (int o = 16; o > 0; o >>= 1)
            p += __shfl_down_sync(0xffffffffu, p, o);
        if (t == 0) s_prefix = p;
    }
    __syncthreads();

    if (i < NN) {
        int o = s_prefix + incl - v;
        g_offs[i] = o;
        g_cur[i] = o;
    }
    if (i == NN - 1) g_offs[NN] = ETOT;
}

// 2 edges per thread: maximize concurrent atomic chains (measured 24.6us
// vs 26.7us at 4/thread)
__global__ void k_scatter(const int* __restrict__ ei) {
    int t = blockIdx.x * blockDim.x + threadIdx.x;
    if (t >= ETOT / 2) return;
    int e = t * 2;
    int s0, s1, d0, d1;
    if (e < EE) {
        int2 sv = *(const int2*)(ei + e);
        int2 dv = *(const int2*)(ei + EE + e);
        s0 = sv.x; s1 = sv.y; d0 = dv.x; d1 = dv.y;
    } else {
        int n = e - EE;
        s0 = n; s1 = n + 1; d0 = n; d1 = n + 1;
    }
    int p0 = atomicAdd(&g_cur[d0], 1);
    int p1 = atomicAdd(&g_cur[d1], 1);
    g_csr_src[p0] = s0;
    g_csr_src[p1] = s1;
}

// ---------------- layer-1 aggregation + fused l2prep --------------------------
// One warp per dst node; batch-of-8-edge choreography (round-10 proven best):
//   weight roles:  lane = e*4 + h  (e = lane>>2 in 0..7, h = lane&3)
//   accum roles:   lane owns channels (2*lane, 2*lane+1), head h_acc = lane>>3
__global__ __launch_bounds__(256) void k_agg1(
    const float* __restrict__ b1, const float* __restrict__ W2,
    const float* __restrict__ as2, const float* __restrict__ ad2) {

    const unsigned FULL = 0xffffffffu;
    int lane = threadIdx.x & 31;
    int n = blockIdx.x * 8 + (threadIdx.x >> 5);
    if (n >= NN) return;

    int h_w = lane & 3;        // head for weight role
    int e_w = lane >> 2;       // edge slot for weight role
    int h_acc = lane >> 3;     // head for accumulation role
    int c = 2 * lane;

    float ad_w = __ldg(g_ad1 + n * 4 + h_w);
    int start = __ldg(g_offs + n);
    int end = __ldg(g_offs + n + 1);

    float acc0 = 0.f, acc1 = 0.f, wsum = 0.f;

    for (int base = start; base < end; base += 8) {
        int li = base + (lane & 7);
        int idx = __ldg(g_csr_src + (li < ETOT ? li : ETOT - 1));

        int s_w = __shfl_sync(FULL, idx, e_w);
        float av = __ldg(g_as1 + s_w * 4 + h_w);
        float w = __expf(lrelu(av + ad_w));
        if (base + e_w >= end) w = 0.f;

        #pragma unroll
        for (int e = 0; e < 8; e++) {
            int s_e = __shfl_sync(FULL, idx, e);
            float w_e = __shfl_sync(FULL, w, e * 4 + h_acc);
            float2 q = __half22float2(
                *(const __half2*)(g_h1h + (size_t)s_e * F1 + c));
            acc0 += w_e * q.x;
            acc1 += w_e * q.y;
            wsum += w_e;
        }
    }

    float inv = 1.0f / (wsum + 1e-16f);
    int c0 = c, c1 = c + 1;
    float v0 = acc0 * inv + b1[c0];
    float v1 = acc1 * inv + b1[c1];
    v0 = v0 > 0.f ? v0 : expm1f(v0);          // ELU
    v1 = v1 > 0.f ? v1 : expm1f(v1);

    float p0 = v0 * W2[c0 * 2 + 0] + v1 * W2[c1 * 2 + 0];
    float p1 = v0 * W2[c0 * 2 + 1] + v1 * W2[c1 * 2 + 1];
    #pragma unroll
    for (int o = 16; o > 0; o >>= 1) {
        p0 += __shfl_down_sync(FULL, p0, o);
        p1 += __shfl_down_sync(FULL, p1, o);
    }
    if (lane == 0) {
        // packed per-source layer-2 state: {h3.x, h3.y, as2, 0}
        float s2v = p0 * as2[0] + p1 * as2[1];
        g_pk2[n] = make_float4(p0, p1, s2v, 0.f);
        g_ad2[n] = p0 * ad2[0] + p1 * ad2[1];
    }
}

// ---------------- layer-2 aggregation + output: half-warp per node ------------
// One float4 LDG per edge carries {h3.x, h3.y, as2} of the source.
__global__ __launch_bounds__(256) void k_agg2(
    float* __restrict__ out, const float* __restrict__ b2) {

    int sub = threadIdx.x & 15;
    int n = blockIdx.x * 16 + (threadIdx.x >> 4);
    if (n >= NN) return;

    float ad = g_ad2[n];
    int start = __ldg(g_offs + n);
    int end = __ldg(g_offs + n + 1);

    float a0 = 0.f, a1 = 0.f, wsum = 0.f;
    for (int i = start + sub; i < end; i += 16) {
        int s = __ldg(g_csr_src + i);
        float4 pk = g_pk2[s];
        float w = __expf(lrelu(pk.z + ad));
        a0 += w * pk.x;
        a1 += w * pk.y;
        wsum += w;
    }
    #pragma unroll
    for (int o = 8; o > 0; o >>= 1) {
        a0   += __shfl_down_sync(0xffffffffu, a0, o, 16);
        a1   += __shfl_down_sync(0xffffffffu, a1, o, 16);
        wsum += __shfl_down_sync(0xffffffffu, wsum, o, 16);
    }
    if (sub == 0) {
        float inv = 1.0f / (wsum + 1e-16f);
        out[n * 2 + 0] = a0 * inv + b2[0];
        out[n * 2 + 1] = a1 * inv + b2[1];
    }
}

// ---------------- launch ------------------------------------------------------
extern "C" void kernel_launch(void* const* d_in, const int* in_sizes, int n_in,
                              void* d_out, int out_size) {
    const float* x    = (const float*)d_in[0];
    const int*   ei   = (const int*)  d_in[1];
    const float* W1   = (const float*)d_in[2];
    const float* as1  = (const float*)d_in[3];
    const float* ad1  = (const float*)d_in[4];
    const float* b1   = (const float*)d_in[5];
    const float* W2   = (const float*)d_in[6];
    const float* as2  = (const float*)d_in[7];
    const float* ad2  = (const float*)d_in[8];
    const float* b2   = (const float*)d_in[9];
    float* out = (float*)d_out;

    // One-time host-side resources (host objects only; no device allocation).
    static cudaStream_t s2 = nullptr;
    static cudaEvent_t evFork = nullptr, evJoin = nullptr;
    if (!s2) {
        cudaStreamCreateWithFlags(&s2, cudaStreamNonBlocking);
        cudaEventCreateWithFlags(&evFork, cudaEventDisableTiming);
        cudaEventCreateWithFlags(&evJoin, cudaEventDisableTiming);
        cudaFuncSetAttribute(k_gemm1,
            cudaFuncAttributeMaxDynamicSharedMemorySize, GEMM_SMEM);
    }

    const int T = 256;

    // Fork: CSR build chain (depends only on ei) on s2, concurrent with GEMM.
    cudaEventRecord(evFork, 0);
    cudaStreamWaitEvent(s2, evFork, 0);

    k_gemm1<<<(NN + GN - 1) / GN, 128, GEMM_SMEM>>>(x, W1, as1, ad1);

    k_count<<<(ETOT / 8 + T - 1) / T, T, 0, s2>>>(ei);
    k_scanF<<<NBLK, SCAN_BLK, 0, s2>>>();
    k_scatter<<<(ETOT / 2 + T - 1) / T, T, 0, s2>>>(ei);

    // Join
    cudaEventRecord(evJoin, s2);
    cudaStreamWaitEvent(0, evJoin, 0);

    k_agg1<<<(NN + 7) / 8, T>>>(b1, W2, as2, ad2);
    k_agg2<<<(NN + 15) / 16, T>>>(out, b2);
}

// round 16
// speedup vs baseline: 1.0513x; 1.0068x over previous
#include <cuda_runtime.h>
#include <cuda_fp16.h>
#include <math.h>

#define NN 100000
#define EE 1600000
#define ETOT (EE + NN)
#define DIM 128
#define HID 16
#define HEADS 4
#define F1 (HEADS * HID)   // 64
#define NEG 0.2f

#define SCAN_BLK 512
#define NBLK ((NN + SCAN_BLK - 1) / SCAN_BLK)   // 196

// gemm tiling: 128 nodes/block, 128 threads, 8 nodes x 8 channels per thread
#define GN 128
#define XPITCH 129
#define GEMM_SMEM ((GN * XPITCH + DIM * F1) * 4)   // 98816 bytes

// ---------------- scratch (static device globals; no allocation) -------------
__device__ __align__(16) __half g_h1h[NN * F1];   // layer-1 features (fp16)
__device__ __align__(16) float g_as1[NN * HEADS];
__device__ __align__(16) float g_ad1[NN * HEADS];
__device__ __align__(16) float4 g_pk2[NN];        // {h3.x, h3.y, as2, 0} per node
__device__ float g_ad2[NN];

__device__ int g_deg[NN];
__device__ int g_offs[NN + 1];
__device__ __align__(16) int g_rank[ETOT];        // per-edge rank within its dst
__device__ int g_bsum[256];
__device__ unsigned long long g_ctr = 0ULL;   // epoch ticket counter (never reset)
__device__ int g_csr_src[ETOT];

// ---------------- helpers ----------------------------------------------------
__device__ __forceinline__ float lrelu(float v) {
    return v > 0.0f ? v : NEG * v;
}

__device__ __forceinline__ unsigned long long packf2(float lo, float hi) {
    unsigned long long r;
    asm("mov.b64 %0, {%1, %2};" : "=l"(r) : "f"(lo), "f"(hi));
    return r;
}
__device__ __forceinline__ void unpackf2(unsigned long long v, float& lo, float& hi) {
    asm("mov.b64 {%0, %1}, %2;" : "=f"(lo), "=f"(hi) : "l"(v));
}
__device__ __forceinline__ void fmaf2(unsigned long long& d, unsigned long long a,
                                      unsigned long long b) {
    asm("fma.rn.f32x2 %0, %1, %2, %0;" : "+l"(d) : "l"(a), "l"(b));
}

// ---------------- kernels ----------------------------------------------------

// h1 = x @ W1 (register-tiled 8 nodes x 8 ch per thread, packed f32x2 FMA).
__global__ __launch_bounds__(128, 2) void k_gemm1(
    const float* __restrict__ x, const float* __restrict__ W1,
    const float* __restrict__ asrc, const float* __restrict__ adst) {

    extern __shared__ float sm[];
    float* xs = sm;                    // [GN][XPITCH]
    float* Ws = sm + GN * XPITCH;      // [DIM][F1] row-major

    int tid = threadIdx.x;
    int n0 = blockIdx.x * GN;

    #pragma unroll
    for (int i = tid; i < DIM * F1 / 4; i += 128)
        ((float4*)Ws)[i] = ((const float4*)W1)[i];

    for (int i = tid; i < GN * 32; i += 128) {
        int r = i >> 5, c4 = i & 31;
        float4 v = (n0 + r < NN)
                 ? ((const float4*)(x + (size_t)(n0 + r) * DIM))[c4]
                 : make_float4(0.f, 0.f, 0.f, 0.f);
        float* dp = xs + r * XPITCH + c4 * 4;
        dp[0] = v.x; dp[1] = v.y; dp[2] = v.z; dp[3] = v.w;
    }
    __syncthreads();

    int ct = tid & 7;
    int nt = tid >> 3;

    unsigned long long acc[8][4];
    #pragma unroll
    for (int j = 0; j < 8; j++)
        #pragma unroll
        for (int p = 0; p < 4; p++) acc[j][p] = 0ULL;

    const float* xb = xs + nt * 8 * XPITCH;

    #pragma unroll 2
    for (int k = 0; k < DIM; k++) {
        float4 w0 = *(const float4*)(Ws + k * F1 + ct * 8);
        float4 w1 = *(const float4*)(Ws + k * F1 + ct * 8 + 4);
        unsigned long long wp[4];
        wp[0] = packf2(w0.x, w0.y);
        wp[1] = packf2(w0.z, w0.w);
        wp[2] = packf2(w1.x, w1.y);
        wp[3] = packf2(w1.z, w1.w);
        #pragma unroll
        for (int j = 0; j < 8; j++) {
            float xv = xb[j * XPITCH + k];
            unsigned long long xx = packf2(xv, xv);
            fmaf2(acc[j][0], xx, wp[0]);
            fmaf2(acc[j][1], xx, wp[1]);
            fmaf2(acc[j][2], xx, wp[2]);
            fmaf2(acc[j][3], xx, wp[3]);
        }
    }

    float ar[8], dr[8];
    #pragma unroll
    for (int i = 0; i < 8; i++) {
        ar[i] = __ldg(asrc + ct * 8 + i);
        dr[i] = __ldg(adst + ct * 8 + i);
    }

    #pragma unroll
    for (int j = 0; j < 8; j++) {
        int n = n0 + nt * 8 + j;
        float a[8];
        unpackf2(acc[j][0], a[0], a[1]);
        unpackf2(acc[j][1], a[2], a[3]);
        unpackf2(acc[j][2], a[4], a[5]);
        unpackf2(acc[j][3], a[6], a[7]);

        float ps = 0.f, pd = 0.f;
        #pragma unroll
        for (int i = 0; i < 8; i++) {
            ps += a[i] * ar[i];
            pd += a[i] * dr[i];
        }
        ps += __shfl_xor_sync(0xffffffffu, ps, 1);
        pd += __shfl_xor_sync(0xffffffffu, pd, 1);

        if (n < NN) {
            union { __half2 h2[4]; uint4 u; } pk;
            pk.h2[0] = __floats2half2_rn(a[0], a[1]);
            pk.h2[1] = __floats2half2_rn(a[2], a[3]);
            pk.h2[2] = __floats2half2_rn(a[4], a[5]);
            pk.h2[3] = __floats2half2_rn(a[6], a[7]);
            *(uint4*)(g_h1h + (size_t)n * F1 + ct * 8) = pk.u;
            if ((ct & 1) == 0) {
                int h = ct >> 1;
                g_as1[n * HEADS + h] = ps;
                g_ad1[n * HEADS + h] = pd;
            }
        }
    }
}

// ---------------- CSR build ---------------------------------------------------
// Count + record per-edge rank (rank = this edge's position within its dst
// bucket). 8 edges per thread; rank stores are coalesced int4.
__global__ void k_count(const int* __restrict__ ei) {
    int t = blockIdx.x * blockDim.x + threadIdx.x;
    if (t >= ETOT / 8) return;
    int e = t * 8;
    int r[8];
    if (e < EE) {
        int4 a = *(const int4*)(ei + EE + e);
        int4 b = *(const int4*)(ei + EE + e + 4);
        r[0] = atomicAdd(&g_deg[a.x], 1);
        r[1] = atomicAdd(&g_deg[a.y], 1);
        r[2] = atomicAdd(&g_deg[a.z], 1);
        r[3] = atomicAdd(&g_deg[a.w], 1);
        r[4] = atomicAdd(&g_deg[b.x], 1);
        r[5] = atomicAdd(&g_deg[b.y], 1);
        r[6] = atomicAdd(&g_deg[b.z], 1);
        r[7] = atomicAdd(&g_deg[b.w], 1);
    } else {
        int n = e - EE;
        #pragma unroll
        for (int j = 0; j < 8; j++) r[j] = atomicAdd(&g_deg[n + j], 1);
    }
    *(int4*)(g_rank + e)     = make_int4(r[0], r[1], r[2], r[3]);
    *(int4*)(g_rank + e + 4) = make_int4(r[4], r[5], r[6], r[7]);
}

// Fused single-pass scan; all NBLK=196 blocks resident -> grid spin is safe.
// Also zeroes g_deg for the next replay (static init covers the first call).
__global__ __launch_bounds__(SCAN_BLK) void k_scanF() {
    __shared__ int sh[SCAN_BLK];
    __shared__ int s_prefix;
    int t = threadIdx.x;
    int b = blockIdx.x;
    int i = b * SCAN_BLK + t;
    int v = 0;
    if (i < NN) { v = g_deg[i]; g_deg[i] = 0; }
    sh[t] = v;
    __syncthreads();
    #pragma unroll
    for (int off = 1; off < SCAN_BLK; off <<= 1) {
        int add = (t >= off) ? sh[t - off] : 0;
        __syncthreads();
        sh[t] += add;
        __syncthreads();
    }
    int incl = sh[t];

    if (t == SCAN_BLK - 1) {
        g_bsum[b] = incl;
        __threadfence();
        unsigned long long old = atomicAdd(&g_ctr, 1ULL);
        unsigned long long target = (old / NBLK + 1ULL) * NBLK;
        while (atomicAdd(&g_ctr, 0ULL) < target) { }
    }
    __syncthreads();

    if (t < 32) {
        volatile int* vb = g_bsum;
        int p = 0;
        for (int j = t; j < b; j += 32) p += vb[j];
        #pragma unroll
        for (int o = 16; o > 0; o >>= 1)
            p += __shfl_down_sync(0xffffffffu, p, o);
        if (t == 0) s_prefix = p;
    }
    __syncthreads();

    if (i < NN) g_offs[i] = s_prefix + incl - v;
    if (i == NN - 1) g_offs[NN] = ETOT;
}

// Atomic-free scatter: pos = offs[dst] + rank[e]. 4 edges per thread.
__global__ void k_scatter(const int* __restrict__ ei) {
    int t = blockIdx.x * blockDim.x + threadIdx.x;
    if (t >= ETOT / 4) return;
    int e = t * 4;
    int s[4], d[4];
    if (e < EE) {
        int4 s4 = *(const int4*)(ei + e);
        int4 d4 = *(const int4*)(ei + EE + e);
        s[0]=s4.x; s[1]=s4.y; s[2]=s4.z; s[3]=s4.w;
        d[0]=d4.x; d[1]=d4.y; d[2]=d4.z; d[3]=d4.w;
    } else {
        int n = e - EE;
        #pragma unroll
        for (int j = 0; j < 4; j++) { s[j] = n + j; d[j] = n + j; }
    }
    int4 rk = *(const int4*)(g_rank + e);
    int pos[4];
    pos[0] = __ldg(g_offs + d[0]) + rk.x;
    pos[1] = __ldg(g_offs + d[1]) + rk.y;
    pos[2] = __ldg(g_offs + d[2]) + rk.z;
    pos[3] = __ldg(g_offs + d[3]) + rk.w;
    #pragma unroll
    for (int j = 0; j < 4; j++) g_csr_src[pos[j]] = s[j];
}

// ---------------- layer-1 aggregation + fused l2prep --------------------------
// One warp per dst node; batch-of-8-edge choreography (round-10 proven best):
//   weight roles:  lane = e*4 + h  (e = lane>>2 in 0..7, h = lane&3)
//   accum roles:   lane owns channels (2*lane, 2*lane+1), head h_acc = lane>>3
__global__ __launch_bounds__(256) void k_agg1(
    const float* __restrict__ b1, const float* __restrict__ W2,
    const float* __restrict__ as2, const float* __restrict__ ad2) {

    const unsigned FULL = 0xffffffffu;
    int lane = threadIdx.x & 31;
    int n = blockIdx.x * 8 + (threadIdx.x >> 5);
    if (n >= NN) return;

    int h_w = lane & 3;        // head for weight role
    int e_w = lane >> 2;       // edge slot for weight role
    int h_acc = lane >> 3;     // head for accumulation role
    int c = 2 * lane;

    float ad_w = __ldg(g_ad1 + n * 4 + h_w);
    int start = __ldg(g_offs + n);
    int end = __ldg(g_offs + n + 1);

    float acc0 = 0.f, acc1 = 0.f, wsum = 0.f;

    for (int base = start; base < end; base += 8) {
        int li = base + (lane & 7);
        int idx = __ldg(g_csr_src + (li < ETOT ? li : ETOT - 1));

        int s_w = __shfl_sync(FULL, idx, e_w);
        float av = __ldg(g_as1 + s_w * 4 + h_w);
        float w = __expf(lrelu(av + ad_w));
        if (base + e_w >= end) w = 0.f;

        #pragma unroll
        for (int e = 0; e < 8; e++) {
            int s_e = __shfl_sync(FULL, idx, e);
            float w_e = __shfl_sync(FULL, w, e * 4 + h_acc);
            float2 q = __half22float2(
                *(const __half2*)(g_h1h + (size_t)s_e * F1 + c));
            acc0 += w_e * q.x;
            acc1 += w_e * q.y;
            wsum += w_e;
        }
    }

    float inv = 1.0f / (wsum + 1e-16f);
    int c0 = c, c1 = c + 1;
    float v0 = acc0 * inv + b1[c0];
    float v1 = acc1 * inv + b1[c1];
    v0 = v0 > 0.f ? v0 : expm1f(v0);          // ELU
    v1 = v1 > 0.f ? v1 : expm1f(v1);

    float p0 = v0 * W2[c0 * 2 + 0] + v1 * W2[c1 * 2 + 0];
    float p1 = v0 * W2[c0 * 2 + 1] + v1 * W2[c1 * 2 + 1];
    #pragma unroll
    for (int o = 16; o > 0; o >>= 1) {
        p0 += __shfl_down_sync(FULL, p0, o);
        p1 += __shfl_down_sync(FULL, p1, o);
    }
    if (lane == 0) {
        // packed per-source layer-2 state: {h3.x, h3.y, as2, 0}
        float s2v = p0 * as2[0] + p1 * as2[1];
        g_pk2[n] = make_float4(p0, p1, s2v, 0.f);
        g_ad2[n] = p0 * ad2[0] + p1 * ad2[1];
    }
}

// ---------------- layer-2 aggregation + output: half-warp per node ------------
// One float4 LDG per edge carries {h3.x, h3.y, as2} of the source.
__global__ __launch_bounds__(256) void k_agg2(
    float* __restrict__ out, const float* __restrict__ b2) {

    int sub = threadIdx.x & 15;
    int n = blockIdx.x * 16 + (threadIdx.x >> 4);
    if (n >= NN) return;

    float ad = g_ad2[n];
    int start = __ldg(g_offs + n);
    int end = __ldg(g_offs + n + 1);

    float a0 = 0.f, a1 = 0.f, wsum = 0.f;
    for (int i = start + sub; i < end; i += 16) {
        int s = __ldg(g_csr_src + i);
        float4 pk = g_pk2[s];
        float w = __expf(lrelu(pk.z + ad));
        a0 += w * pk.x;
        a1 += w * pk.y;
        wsum += w;
    }
    #pragma unroll
    for (int o = 8; o > 0; o >>= 1) {
        a0   += __shfl_down_sync(0xffffffffu, a0, o, 16);
        a1   += __shfl_down_sync(0xffffffffu, a1, o, 16);
        wsum += __shfl_down_sync(0xffffffffu, wsum, o, 16);
    }
    if (sub == 0) {
        float inv = 1.0f / (wsum + 1e-16f);
        out[n * 2 + 0] = a0 * inv + b2[0];
        out[n * 2 + 1] = a1 * inv + b2[1];
    }
}

// ---------------- launch ------------------------------------------------------
extern "C" void kernel_launch(void* const* d_in, const int* in_sizes, int n_in,
                              void* d_out, int out_size) {
    const float* x    = (const float*)d_in[0];
    const int*   ei   = (const int*)  d_in[1];
    const float* W1   = (const float*)d_in[2];
    const float* as1  = (const float*)d_in[3];
    const float* ad1  = (const float*)d_in[4];
    const float* b1   = (const float*)d_in[5];
    const float* W2   = (const float*)d_in[6];
    const float* as2  = (const float*)d_in[7];
    const float* ad2  = (const float*)d_in[8];
    const float* b2   = (const float*)d_in[9];
    float* out = (float*)d_out;

    // One-time host-side resources (host objects only; no device allocation).
    static cudaStream_t s2 = nullptr;
    static cudaEvent_t evFork = nullptr, evJoin = nullptr;
    if (!s2) {
        cudaStreamCreateWithFlags(&s2, cudaStreamNonBlocking);
        cudaEventCreateWithFlags(&evFork, cudaEventDisableTiming);
        cudaEventCreateWithFlags(&evJoin, cudaEventDisableTiming);
        cudaFuncSetAttribute(k_gemm1,
            cudaFuncAttributeMaxDynamicSharedMemorySize, GEMM_SMEM);
    }

    const int T = 256;

    // Fork: CSR build chain (depends only on ei) on s2, concurrent with GEMM.
    cudaEventRecord(evFork, 0);
    cudaStreamWaitEvent(s2, evFork, 0);

    k_gemm1<<<(NN + GN - 1) / GN, 128, GEMM_SMEM>>>(x, W1, as1, ad1);

    k_count<<<(ETOT / 8 + T - 1) / T, T, 0, s2>>>(ei);
    k_scanF<<<NBLK, SCAN_BLK, 0, s2>>>();
    k_scatter<<<(ETOT / 4 + T - 1) / T, T, 0, s2>>>(ei);

    // Join
    cudaEventRecord(evJoin, s2);
    cudaStreamWaitEvent(0, evJoin, 0);

    k_agg1<<<(NN + 7) / 8, T>>>(b1, W2, as2, ad2);
    k_agg2<<<(NN + 15) / 16, T>>>(out, b2);
}